// round 3
// baseline (speedup 1.0000x reference)
#include <cuda_runtime.h>
#include <math.h>

#define B_      32
#define N_      325
#define L_      12
#define D_      128
#define H_      8
#define DK      16
#define BN      (B_*N_)        // 10400
#define ROWS    (BN*L_)        // 124800
#define MAXREL  11
#define LL      (L_*L_)        // 144
#define HLL     (H_*LL)        // 1152
#define T_      4              // tiles per block
#define NB      (BN/T_)        // 2600 blocks
#define THLL    (T_*HLL)       // 4608

typedef unsigned long long u64t;

// ---- static device scratch ----
// Packed weights: b64 element [d2][c] = (w[c][2*d2], w[c][2*d2+1])
__device__ __align__(16) float g_Wkp[4][D_*D_];
__device__ __align__(16) float g_K2[LL*DK];
__device__ __align__(16) float g_V2[LL*DK];
__device__ __align__(16) float g_ctx[(size_t)ROWS*D_];
__device__ __align__(16) float g_psum[D_*BN];
__device__ __align__(16) float g_psumsq[D_*BN];
__device__ float g_scale[D_];
__device__ float g_shift[D_];

__device__ __forceinline__ u64t fma2(u64t a, u64t b, u64t c) {
    u64t d; asm("fma.rn.f32x2 %0, %1, %2, %3;" : "=l"(d) : "l"(a), "l"(b), "l"(c)); return d;
}
__device__ __forceinline__ u64t add2(u64t a, u64t b) {
    u64t d; asm("add.rn.f32x2 %0, %1, %2;" : "=l"(d) : "l"(a), "l"(b)); return d;
}
__device__ __forceinline__ u64t splat2(float a) {
    u64t d; asm("mov.b64 %0, {%1, %1};" : "=l"(d) : "f"(a)); return d;
}
__device__ __forceinline__ float hsum2(u64t v) {
    float lo, hi; asm("mov.b64 {%0,%1}, %2;" : "=f"(lo), "=f"(hi) : "l"(v)); return lo + hi;
}
__device__ __forceinline__ float2 unpack2(u64t v) {
    float lo, hi; asm("mov.b64 {%0,%1}, %2;" : "=f"(lo), "=f"(hi) : "l"(v)); return make_float2(lo, hi);
}

// ---------------------------------------------------------------------------
// Kernel 1: weight-norm (packed layout) + rel-position tables
// ---------------------------------------------------------------------------
__global__ void prep_kernel(const float* __restrict__ wq_v, const float* __restrict__ wq_g,
                            const float* __restrict__ wk_v, const float* __restrict__ wk_g,
                            const float* __restrict__ wv_v, const float* __restrict__ wv_g,
                            const float* __restrict__ fc_v, const float* __restrict__ fc_g,
                            const float* __restrict__ rel_k, const float* __restrict__ rel_v) {
    int blk = blockIdx.x;
    if (blk < 4) {
        const float* v; const float* g;
        switch (blk) {
            case 0: v = wq_v; g = wq_g; break;
            case 1: v = wk_v; g = wk_g; break;
            case 2: v = wv_v; g = wv_g; break;
            default: v = fc_v; g = fc_g; break;
        }
        int r = threadIdx.x;
        float s = 0.f;
        for (int d = 0; d < D_; d++) { float x = v[r*D_ + d]; s += x*x; }
        float sc = g[r] * rsqrtf(s);
        for (int d2 = 0; d2 < 64; d2++) {
            g_Wkp[blk][(d2*128 + r)*2 + 0] = v[r*D_ + 2*d2 + 0] * sc;
            g_Wkp[blk][(d2*128 + r)*2 + 1] = v[r*D_ + 2*d2 + 1] * sc;
        }
    } else {
        for (int t = threadIdx.x; t < LL; t += blockDim.x) {
            int q = t / L_, k = t % L_;
            int dist = max(-MAXREL, min(MAXREL, k - q));
            int row = dist + MAXREL;
            for (int d = 0; d < DK; d++) {
                g_K2[t*DK + d] = rel_k[row*DK + d];
                g_V2[t*DK + d] = rel_v[row*DK + d];
            }
        }
    }
}

// ---------------------------------------------------------------------------
// 12x128x128 GEMM tile: x(12x128, smem) @ W^T, thread owns channel pair (2p,2p+1)
// and ALL 12 rows -> each weight LDG amortized over 12 rows (48 FFMA2).
// ---------------------------------------------------------------------------
__device__ __forceinline__ void gemm_rows12(const float* __restrict__ x, int m, int p,
                                            float2 res[12]) {
    const ulonglong2* __restrict__ Wp = (const ulonglong2*)(g_Wkp[m]);
    u64t acc0[12], acc1[12];
    #pragma unroll
    for (int r = 0; r < 12; r++) { acc0[r] = 0; acc1[r] = 0; }
    #pragma unroll 2
    for (int i = 0; i < 32; i++) {          // 4 K-values per iter
        ulonglong2 w0 = Wp[(2*i+0)*64 + p];
        ulonglong2 w1 = Wp[(2*i+1)*64 + p];
        #pragma unroll
        for (int r = 0; r < 12; r++) {
            ulonglong2 xa = ((const ulonglong2*)(x + r*D_))[i];   // broadcast LDS.128
            acc0[r] = fma2(xa.x, w0.x, acc0[r]);
            acc1[r] = fma2(xa.x, w0.y, acc1[r]);
            acc0[r] = fma2(xa.y, w1.x, acc0[r]);
            acc1[r] = fma2(xa.y, w1.y, acc1[r]);
        }
    }
    #pragma unroll
    for (int r = 0; r < 12; r++) res[r] = make_float2(hsum2(acc0[r]), hsum2(acc1[r]));
}

// ---------------------------------------------------------------------------
// Kernel 2: fused attention, 4 (b,n) tiles per block
// ---------------------------------------------------------------------------
__global__ __launch_bounds__(256, 1) void attn_kernel(const float* __restrict__ inQ,
                                                      const float* __restrict__ inK,
                                                      const float* __restrict__ inV,
                                                      const float* __restrict__ w1,
                                                      const float* __restrict__ w2,
                                                      float* __restrict__ attn_out) {
    extern __shared__ __align__(16) float smem[];
    float* s_in = smem;                 // 4*12*128 = 6144   (aliased as s_at later)
    float* s_q  = smem + 6144;          // 6144
    float* s_k  = s_q  + 6144;          // 6144
    float* s_v  = s_k  + 6144;          // 6144
    float* s_sc = s_v  + 6144;          // 4608             (aliased as s_at2 later)
    float* s_w1 = s_sc + THLL;          // 64
    float* s_w2 = s_w1 + 64;            // 64
    float* s_at  = s_in;
    float* s_at2 = s_sc;

    const int tid = threadIdx.x;
    const int p   = tid & 63;           // channel pair (2p, 2p+1)
    const int g   = tid >> 6;           // tile within block
    const int bn0 = blockIdx.x * T_;
    const int bn  = bn0 + g;

    if (tid < 64) { s_w1[tid] = w1[tid]; s_w2[tid] = w2[tid]; }

    // ---- projections: Q,K,V for 4 tiles ----
    for (int m = 0; m < 3; m++) {
        const float* src = (m == 0 ? inQ : (m == 1 ? inK : inV)) + (size_t)bn0 * L_ * D_;
        float* dst = (m == 0 ? s_q : (m == 1 ? s_k : s_v));
        for (int i = tid; i < (T_*L_*D_)/4; i += 256)
            ((float4*)s_in)[i] = ((const float4*)src)[i];
        __syncthreads();

        float2 res[12];
        gemm_rows12(s_in + g*L_*D_, m, p, res);
        float2* drow = (float2*)(dst + g*L_*D_) + p;
        #pragma unroll
        for (int r = 0; r < 12; r++) drow[r*64] = res[r];
        __syncthreads();
    }

    // ---- scores: s1 (QK^T per head) + s2 (rel keys), scaled ----
    for (int idx = tid; idx < THLL; idx += 256) {
        int t = idx / HLL, r = idx % HLL;
        int h = r / LL, rem = r % LL;
        int i = rem / L_, j = rem % L_;
        const float4* qi = (const float4*)(s_q + t*L_*D_ + i*D_ + h*DK);
        const float4* kj = (const float4*)(s_k + t*L_*D_ + j*D_ + h*DK);
        const float4* k2 = (const float4*)(g_K2 + rem*DK);
        float s = 0.f;
        #pragma unroll
        for (int d4 = 0; d4 < 4; d4++) {
            float4 q4 = qi[d4], kk = kj[d4], r4 = k2[d4];
            s += q4.x*(kk.x+r4.x) + q4.y*(kk.y+r4.y) + q4.z*(kk.z+r4.z) + q4.w*(kk.w+r4.w);
        }
        s_sc[idx] = s * 0.25f;
    }
    __syncthreads();

    // ---- cross-head mix (w1) + leaky relu ----
    for (int idx = tid; idx < THLL; idx += 256) {
        int t = idx / HLL, r = idx % HLL;
        int gh = r / LL, rem = r % LL;
        const float* base = s_sc + t*HLL + rem;
        float s = 0.f;
        #pragma unroll
        for (int h = 0; h < H_; h++) s += base[h*LL] * s_w1[h*H_ + gh];
        s_at[idx] = (s > 0.f) ? s : 0.2f * s;
    }
    __syncthreads();

    // ---- softmax over k (4*96 rows of length 12) ----
    for (int rowid = tid; rowid < T_*H_*L_; rowid += 256) {
        float* row = s_at + rowid * L_;
        float mx = row[0];
        #pragma unroll
        for (int j = 1; j < L_; j++) mx = fmaxf(mx, row[j]);
        float sum = 0.f;
        #pragma unroll
        for (int j = 0; j < L_; j++) { float e = __expf(row[j] - mx); row[j] = e; sum += e; }
        float inv = 1.f / sum;
        #pragma unroll
        for (int j = 0; j < L_; j++) row[j] *= inv;
    }
    __syncthreads();

    // ---- cross-head mix (w2) ----
    for (int idx = tid; idx < THLL; idx += 256) {
        int t = idx / HLL, r = idx % HLL;
        int gh = r / LL, rem = r % LL;
        const float* base = s_at + t*HLL + rem;
        float s = 0.f;
        #pragma unroll
        for (int h = 0; h < H_; h++) s += base[h*LL] * s_w2[h*H_ + gh];
        s_at2[idx] = s;
    }
    __syncthreads();

    // ---- attn_ret[q, (bn*H + h), k] ----
    for (int idx = tid; idx < THLL; idx += 256) {
        int t = idx / HLL, r = idx % HLL;
        int h = r / LL, rem = r % LL;
        int i = rem / L_, j = rem % L_;
        attn_out[(size_t)i * ((size_t)BN*H_*L_) + ((size_t)(bn0+t)*H_ + h)*L_ + j] = s_at2[idx];
    }

    // ---- context: c1 (attn @ V) + c2 (attn @ rel V), group g owns tile g ----
    const int hh = p >> 3;              // head of channels 2p,2p+1
    const int dd = (2*p) & 15;          // within-head dim (even)
    u64t vj[12];
    #pragma unroll
    for (int j = 0; j < L_; j++) vj[j] = *(const u64t*)(s_v + g*L_*D_ + j*D_ + 2*p);
    const float* at = s_at2 + g*HLL + hh*LL;
    float* ctxp = g_ctx + (size_t)bn * L_ * D_;
    u64t sum2 = 0, sq2 = 0;
    #pragma unroll
    for (int i = 0; i < L_; i++) {
        u64t acc = 0;
        #pragma unroll
        for (int j = 0; j < L_; j++) {
            float a = at[i*L_ + j];
            u64t v2 = *(const u64t*)(g_V2 + (i*L_ + j)*DK + dd);
            acc = fma2(splat2(a), add2(vj[j], v2), acc);
        }
        ((float2*)(ctxp + i*D_))[p] = unpack2(acc);
        sum2 = add2(sum2, acc);
        sq2  = fma2(acc, acc, sum2 == sum2 ? sq2 : sq2);  // keep simple below
    }
    // recompute sq cleanly (avoid trick above): fold into the loop properly
    // (sq2 updated in-loop; the conditional above is identity)
    float2 sm = unpack2(sum2), sq = unpack2(sq2);
    g_psum  [(2*p+0)*BN + bn] = sm.x;
    g_psum  [(2*p+1)*BN + bn] = sm.y;
    g_psumsq[(2*p+0)*BN + bn] = sq.x;
    g_psumsq[(2*p+1)*BN + bn] = sq.y;
}

// ---------------------------------------------------------------------------
// Kernel 3: finalize BN stats
// ---------------------------------------------------------------------------
__global__ void stats_kernel(const float* __restrict__ gamma, const float* __restrict__ beta) {
    const int c = blockIdx.x;
    __shared__ float sh[256], shq[256];
    float s = 0.f, ss = 0.f;
    for (int t = threadIdx.x; t < BN; t += 256) {
        s  += g_psum[c*BN + t];
        ss += g_psumsq[c*BN + t];
    }
    sh[threadIdx.x] = s; shq[threadIdx.x] = ss;
    __syncthreads();
    for (int st = 128; st > 0; st >>= 1) {
        if (threadIdx.x < st) {
            sh[threadIdx.x]  += sh[threadIdx.x + st];
            shq[threadIdx.x] += shq[threadIdx.x + st];
        }
        __syncthreads();
    }
    if (threadIdx.x == 0) {
        const float invN = 1.f / (float)ROWS;
        float mean = sh[0] * invN;
        float var  = shq[0] * invN - mean*mean;
        float sc = rsqrtf(var + 1e-5f) * gamma[c];
        g_scale[c] = sc;
        g_shift[c] = beta[c] - mean * sc;
    }
}

// ---------------------------------------------------------------------------
// Kernel 4: BN-apply + fc GEMM + ReLU + residual (4 tiles per block)
// ---------------------------------------------------------------------------
__global__ __launch_bounds__(256, 1) void out_kernel(const float* __restrict__ inV,
                                                     float* __restrict__ out) {
    __shared__ __align__(16) float s_x[T_*L_*D_];
    __shared__ float s_scale[D_], s_shift[D_];
    const int tid = threadIdx.x;
    const int p   = tid & 63;
    const int g   = tid >> 6;
    const int bn0 = blockIdx.x * T_;
    const int bn  = bn0 + g;

    if (tid < D_) { s_scale[tid] = g_scale[tid]; s_shift[tid] = g_shift[tid]; }
    __syncthreads();

    const float4* ctxp = (const float4*)(g_ctx + (size_t)bn0 * L_ * D_);
    const float4* sc4 = (const float4*)s_scale;
    const float4* sh4 = (const float4*)s_shift;
    for (int i = tid; i < (T_*L_*D_)/4; i += 256) {
        float4 x = ctxp[i];
        float4 sc = sc4[i & 31], sh = sh4[i & 31];
        x.x = x.x*sc.x + sh.x; x.y = x.y*sc.y + sh.y;
        x.z = x.z*sc.z + sh.z; x.w = x.w*sc.w + sh.w;
        ((float4*)s_x)[i] = x;
    }
    __syncthreads();

    float2 res[12];
    gemm_rows12(s_x + g*L_*D_, 3, p, res);

    const float2* vrow = (const float2*)(inV + (size_t)bn * L_ * D_) + p;
    float2* orow = (float2*)(out + (size_t)bn * L_ * D_) + p;
    #pragma unroll
    for (int r = 0; r < 12; r++) {
        float2 v = vrow[r*64];
        float2 o;
        o.x = fmaxf(res[r].x, 0.f) + v.x;
        o.y = fmaxf(res[r].y, 0.f) + v.y;
        orow[r*64] = o;
    }
}

// ---------------------------------------------------------------------------
extern "C" void kernel_launch(void* const* d_in, const int* in_sizes, int n_in,
                              void* d_out, int out_size) {
    const float* inQ   = (const float*)d_in[0];
    const float* inK   = (const float*)d_in[1];
    const float* inV   = (const float*)d_in[2];
    const float* wq_v  = (const float*)d_in[3];
    const float* wq_g  = (const float*)d_in[4];
    const float* wk_v  = (const float*)d_in[5];
    const float* wk_g  = (const float*)d_in[6];
    const float* wv_v  = (const float*)d_in[7];
    const float* wv_g  = (const float*)d_in[8];
    const float* fc_v  = (const float*)d_in[9];
    const float* fc_g  = (const float*)d_in[10];
    const float* rel_k = (const float*)d_in[11];
    const float* rel_v = (const float*)d_in[12];
    const float* w1    = (const float*)d_in[13];
    const float* w2    = (const float*)d_in[14];
    const float* gamma = (const float*)d_in[15];
    const float* beta  = (const float*)d_in[16];

    float* out      = (float*)d_out;
    float* attn_out = out + (size_t)ROWS * D_;

    const int smem_bytes = (6144*4 + THLL + 128) * sizeof(float);   // 117,248 B
    cudaFuncSetAttribute(attn_kernel, cudaFuncAttributeMaxDynamicSharedMemorySize, smem_bytes);

    prep_kernel<<<5, 128>>>(wq_v, wq_g, wk_v, wk_g, wv_v, wv_g, fc_v, fc_g, rel_k, rel_v);
    attn_kernel<<<NB, 256, smem_bytes>>>(inQ, inK, inV, w1, w2, attn_out);
    stats_kernel<<<D_, 256>>>(gamma, beta);
    out_kernel<<<NB, 256>>>(inV, out);
}

// round 4
// speedup vs baseline: 1.5151x; 1.5151x over previous
#include <cuda_runtime.h>
#include <math.h>

#define B_      32
#define N_      325
#define L_      12
#define D_      128
#define H_      8
#define DK      16
#define BN      (B_*N_)        // 10400
#define ROWS    (BN*L_)        // 124800
#define MAXREL  11
#define LL      (L_*L_)        // 144
#define HLL     (H_*LL)        // 1152
#define TP      4              // tiles per block for GEMM kernels
#define NBP     (BN/TP)        // 2600
#define PITCH   132            // pitched row stride (floats) for Q/K/V smem in mid
#define VP      20             // pitched stride for K2/V2 tables in smem

typedef unsigned long long u64t;

// ---- static device scratch ----
// Packed weights: ulonglong2[d2*64 + p] = { ch 2p:(K 2d2,2d2+1), ch 2p+1:(K 2d2,2d2+1) }
__device__ __align__(16) float g_Wkp[4][D_*D_];
__device__ __align__(16) float g_K2[LL*DK];
__device__ __align__(16) float g_V2[LL*DK];
__device__ __align__(16) float g_q[(size_t)ROWS*D_];
__device__ __align__(16) float g_k[(size_t)ROWS*D_];
__device__ __align__(16) float g_v[(size_t)ROWS*D_];
__device__ __align__(16) float g_ctx[(size_t)ROWS*D_];
__device__ __align__(16) float g_psum[D_*BN];
__device__ __align__(16) float g_psumsq[D_*BN];
__device__ float g_scale[D_];
__device__ float g_shift[D_];

__device__ __forceinline__ u64t fma2(u64t a, u64t b, u64t c) {
    u64t d; asm("fma.rn.f32x2 %0, %1, %2, %3;" : "=l"(d) : "l"(a), "l"(b), "l"(c)); return d;
}
__device__ __forceinline__ float hsum2(u64t v) {
    float lo, hi; asm("mov.b64 {%0,%1}, %2;" : "=f"(lo), "=f"(hi) : "l"(v)); return lo + hi;
}

// ---------------------------------------------------------------------------
// Kernel 1: weight-norm (packed layout) + rel-position tables
// ---------------------------------------------------------------------------
__global__ void prep_kernel(const float* __restrict__ wq_v, const float* __restrict__ wq_g,
                            const float* __restrict__ wk_v, const float* __restrict__ wk_g,
                            const float* __restrict__ wv_v, const float* __restrict__ wv_g,
                            const float* __restrict__ fc_v, const float* __restrict__ fc_g,
                            const float* __restrict__ rel_k, const float* __restrict__ rel_v) {
    int blk = blockIdx.x;
    if (blk < 4) {
        const float* v; const float* g;
        switch (blk) {
            case 0: v = wq_v; g = wq_g; break;
            case 1: v = wk_v; g = wk_g; break;
            case 2: v = wv_v; g = wv_g; break;
            default: v = fc_v; g = fc_g; break;
        }
        int r = threadIdx.x;
        float s = 0.f;
        for (int d = 0; d < D_; d++) { float x = v[r*D_ + d]; s += x*x; }
        float sc = g[r] * rsqrtf(s);
        for (int d2 = 0; d2 < 64; d2++) {
            g_Wkp[blk][(d2*128 + r)*2 + 0] = v[r*D_ + 2*d2 + 0] * sc;
            g_Wkp[blk][(d2*128 + r)*2 + 1] = v[r*D_ + 2*d2 + 1] * sc;
        }
    } else {
        for (int t = threadIdx.x; t < LL; t += blockDim.x) {
            int q = t / L_, k = t % L_;
            int dist = max(-MAXREL, min(MAXREL, k - q));
            int row = dist + MAXREL;
            for (int d = 0; d < DK; d++) {
                g_K2[t*DK + d] = rel_k[row*DK + d];
                g_V2[t*DK + d] = rel_v[row*DK + d];
            }
        }
    }
}

// ---------------------------------------------------------------------------
// 12x128x128 GEMM tile: x(12x128, smem, stride 128) @ W^T.
// Thread owns channel pair (2p,2p+1) and all 12 rows. Single-base indexing.
// ---------------------------------------------------------------------------
__device__ __forceinline__ void gemm12(const float* __restrict__ x, const float* __restrict__ W,
                                       int p, float2 res[12]) {
    const ulonglong2* __restrict__ Wp = ((const ulonglong2*)W) + p;
    const ulonglong2* __restrict__ xp = (const ulonglong2*)x;
    u64t a0[12], a1[12];
    #pragma unroll
    for (int r = 0; r < 12; r++) { a0[r] = 0; a1[r] = 0; }
    #pragma unroll 2
    for (int i = 0; i < 32; i++) {
        ulonglong2 w0 = Wp[(2*i+0)*64];
        ulonglong2 w1 = Wp[(2*i+1)*64];
        #pragma unroll
        for (int r = 0; r < 12; r++) {
            ulonglong2 xa = xp[r*32 + i];
            a0[r] = fma2(xa.x, w0.x, a0[r]);
            a1[r] = fma2(xa.x, w0.y, a1[r]);
            a0[r] = fma2(xa.y, w1.x, a0[r]);
            a1[r] = fma2(xa.y, w1.y, a1[r]);
        }
    }
    #pragma unroll
    for (int r = 0; r < 12; r++) res[r] = make_float2(hsum2(a0[r]), hsum2(a1[r]));
}

// ---------------------------------------------------------------------------
// Kernel 2: QKV projections -> global scratch
// ---------------------------------------------------------------------------
__global__ __launch_bounds__(256, 3) void proj_kernel(const float* __restrict__ inQ,
                                                      const float* __restrict__ inK,
                                                      const float* __restrict__ inV) {
    extern __shared__ __align__(16) float s_in[];    // 3 * TP*1536 floats
    const int tid = threadIdx.x;
    const int p   = tid & 63;
    const int g   = tid >> 6;
    const size_t base = (size_t)blockIdx.x * TP * (L_*D_);

    const float4* q4 = (const float4*)(inQ + base);
    const float4* k4 = (const float4*)(inK + base);
    const float4* v4 = (const float4*)(inV + base);
    float4* s4 = (float4*)s_in;
    const int n4 = TP*L_*D_/4;   // 1536
    for (int i = tid; i < n4; i += 256) {
        s4[i]        = q4[i];
        s4[n4 + i]   = k4[i];
        s4[2*n4 + i] = v4[i];
    }
    __syncthreads();

    const float* xt = s_in + g*(L_*D_);
    float2 res[12];
    {
        gemm12(xt, g_Wkp[0], p, res);
        float2* d2 = (float2*)(g_q + base + g*(L_*D_)) + p;
        #pragma unroll
        for (int r = 0; r < 12; r++) d2[r*64] = res[r];
    }
    {
        gemm12(xt + TP*L_*D_, g_Wkp[1], p, res);
        float2* d2 = (float2*)(g_k + base + g*(L_*D_)) + p;
        #pragma unroll
        for (int r = 0; r < 12; r++) d2[r*64] = res[r];
    }
    {
        gemm12(xt + 2*TP*L_*D_, g_Wkp[2], p, res);
        float2* d2 = (float2*)(g_v + base + g*(L_*D_)) + p;
        #pragma unroll
        for (int r = 0; r < 12; r++) d2[r*64] = res[r];
    }
}

// ---------------------------------------------------------------------------
// Kernel 3: attention middle, one (b,n) per block, 128 threads
// ---------------------------------------------------------------------------
__global__ __launch_bounds__(128) void mid_kernel(const float* __restrict__ w1,
                                                  const float* __restrict__ w2,
                                                  float* __restrict__ attn_out) {
    __shared__ __align__(16) float s_q[L_*PITCH];
    __shared__ __align__(16) float s_k[L_*PITCH];
    __shared__ __align__(16) float s_v[L_*PITCH];
    __shared__ __align__(16) float s_k2[LL*VP];
    __shared__ __align__(16) float s_v2[LL*VP];
    __shared__ float s_sc[HLL];
    __shared__ float s_at[HLL];
    __shared__ float s_at2[HLL];
    __shared__ float s_w1[64], s_w2[64];

    const int tid = threadIdx.x;
    const int bn  = blockIdx.x;

    if (tid < 64) { s_w1[tid] = w1[tid]; s_w2[tid] = w2[tid]; }

    // stage Q,K,V tiles into pitched smem (conflict-free row access)
    const float4* gq = (const float4*)(g_q + (size_t)bn * (L_*D_));
    const float4* gk = (const float4*)(g_k + (size_t)bn * (L_*D_));
    const float4* gv = (const float4*)(g_v + (size_t)bn * (L_*D_));
    for (int i = tid; i < 384; i += 128) {       // 12 rows x 32 float4
        int row = i >> 5, c4 = i & 31;
        ((float4*)s_q)[row*33 + c4] = gq[i];
        ((float4*)s_k)[row*33 + c4] = gk[i];
        ((float4*)s_v)[row*33 + c4] = gv[i];
    }
    // stage K2/V2 pitched
    for (int t = tid; t < LL; t += 128) {
        const float4* sk = (const float4*)(g_K2 + t*DK);
        const float4* sv = (const float4*)(g_V2 + t*DK);
        float4* dk = (float4*)(s_k2 + t*VP);
        float4* dv = (float4*)(s_v2 + t*VP);
        #pragma unroll
        for (int j = 0; j < 4; j++) { dk[j] = sk[j]; dv[j] = sv[j]; }
    }
    __syncthreads();

    // ---- scores: s1 + s2, scaled ----
    for (int idx = tid; idx < HLL; idx += 128) {
        int h = idx / LL, rem = idx - h*LL;
        int i = rem / L_, j = rem - i*L_;
        const float4* qi = (const float4*)(s_q + i*PITCH + h*DK);
        const float4* kj = (const float4*)(s_k + j*PITCH + h*DK);
        const float4* k2 = (const float4*)(s_k2 + rem*VP);
        float s = 0.f;
        #pragma unroll
        for (int d4 = 0; d4 < 4; d4++) {
            float4 q4 = qi[d4], kk = kj[d4], r4 = k2[d4];
            s += q4.x*(kk.x+r4.x) + q4.y*(kk.y+r4.y) + q4.z*(kk.z+r4.z) + q4.w*(kk.w+r4.w);
        }
        s_sc[idx] = s * 0.25f;
    }
    __syncthreads();

    // ---- w1 mix + leaky relu ----
    for (int idx = tid; idx < HLL; idx += 128) {
        int gh = idx / LL, rem = idx - gh*LL;
        const float* base = s_sc + rem;
        float s = 0.f;
        #pragma unroll
        for (int h = 0; h < H_; h++) s += base[h*LL] * s_w1[h*H_ + gh];
        s_at[idx] = (s > 0.f) ? s : 0.2f * s;
    }
    __syncthreads();

    // ---- softmax over k: 96 rows of 12 ----
    if (tid < H_*L_) {
        float* row = s_at + tid * L_;
        float mx = row[0];
        #pragma unroll
        for (int j = 1; j < L_; j++) mx = fmaxf(mx, row[j]);
        float sum = 0.f;
        #pragma unroll
        for (int j = 0; j < L_; j++) { float e = __expf(row[j] - mx); row[j] = e; sum += e; }
        float inv = 1.f / sum;
        #pragma unroll
        for (int j = 0; j < L_; j++) row[j] *= inv;
    }
    __syncthreads();

    // ---- w2 mix ----
    for (int idx = tid; idx < HLL; idx += 128) {
        int gh = idx / LL, rem = idx - gh*LL;
        const float* base = s_at + rem;
        float s = 0.f;
        #pragma unroll
        for (int h = 0; h < H_; h++) s += base[h*LL] * s_w2[h*H_ + gh];
        s_at2[idx] = s;
    }
    __syncthreads();

    // ---- attn_ret[q, bn*96 + h*12 + j] (contiguous 384B segments) ----
    for (int idx = tid; idx < HLL; idx += 128) {
        int i = idx / 96, hj = idx - i*96;
        int h = hj / L_, j = hj - h*L_;
        attn_out[(size_t)i * ((size_t)BN*96) + (size_t)bn*96 + hj] = s_at2[h*LL + i*L_ + j];
    }

    // ---- context + BN partials: thread owns channel c ----
    {
        const int c = tid;
        const int h = c >> 4, d = c & 15;
        float vj[12];
        #pragma unroll
        for (int j = 0; j < L_; j++) vj[j] = s_v[j*PITCH + c];
        const float* at = s_at2 + h*LL;
        float* ctxp = g_ctx + (size_t)bn * (L_*D_);
        float sum = 0.f, sq = 0.f;
        #pragma unroll
        for (int i = 0; i < L_; i++) {
            float acc = 0.f;
            #pragma unroll
            for (int j = 0; j < L_; j++)
                acc = fmaf(at[i*L_ + j], vj[j] + s_v2[(i*L_ + j)*VP + d], acc);
            ctxp[i*D_ + c] = acc;
            sum += acc;
            sq = fmaf(acc, acc, sq);
        }
        g_psum  [c*BN + bn] = sum;
        g_psumsq[c*BN + bn] = sq;
    }
}

// ---------------------------------------------------------------------------
// Kernel 4: finalize BN stats
// ---------------------------------------------------------------------------
__global__ void stats_kernel(const float* __restrict__ gamma, const float* __restrict__ beta) {
    const int c = blockIdx.x;
    __shared__ float sh[256], shq[256];
    float s = 0.f, ss = 0.f;
    for (int t = threadIdx.x; t < BN; t += 256) {
        s  += g_psum[c*BN + t];
        ss += g_psumsq[c*BN + t];
    }
    sh[threadIdx.x] = s; shq[threadIdx.x] = ss;
    __syncthreads();
    for (int st = 128; st > 0; st >>= 1) {
        if (threadIdx.x < st) {
            sh[threadIdx.x]  += sh[threadIdx.x + st];
            shq[threadIdx.x] += shq[threadIdx.x + st];
        }
        __syncthreads();
    }
    if (threadIdx.x == 0) {
        const float invN = 1.f / (float)ROWS;
        float mean = sh[0] * invN;
        float var  = shq[0] * invN - mean*mean;
        float sc = rsqrtf(var + 1e-5f) * gamma[c];
        g_scale[c] = sc;
        g_shift[c] = beta[c] - mean * sc;
    }
}

// ---------------------------------------------------------------------------
// Kernel 5: BN-apply + fc GEMM + ReLU + residual
// ---------------------------------------------------------------------------
__global__ __launch_bounds__(256, 3) void out_kernel(const float* __restrict__ inV,
                                                     float* __restrict__ out) {
    __shared__ __align__(16) float s_x[TP*L_*D_];
    __shared__ float s_scale[D_], s_shift[D_];
    const int tid = threadIdx.x;
    const int p   = tid & 63;
    const int g   = tid >> 6;
    const size_t base = (size_t)blockIdx.x * TP * (L_*D_);

    if (tid < D_) { s_scale[tid] = g_scale[tid]; s_shift[tid] = g_shift[tid]; }
    __syncthreads();

    const float4* ctxp = (const float4*)(g_ctx + base);
    const float4* sc4 = (const float4*)s_scale;
    const float4* sh4 = (const float4*)s_shift;
    for (int i = tid; i < (TP*L_*D_)/4; i += 256) {
        float4 x = ctxp[i];
        float4 sc = sc4[i & 31], sh = sh4[i & 31];
        x.x = x.x*sc.x + sh.x; x.y = x.y*sc.y + sh.y;
        x.z = x.z*sc.z + sh.z; x.w = x.w*sc.w + sh.w;
        ((float4*)s_x)[i] = x;
    }
    __syncthreads();

    float2 res[12];
    gemm12(s_x + g*(L_*D_), g_Wkp[3], p, res);

    const float2* vrow = (const float2*)(inV + base + g*(L_*D_)) + p;
    float2* orow = (float2*)(out + base + g*(L_*D_)) + p;
    #pragma unroll
    for (int r = 0; r < 12; r++) {
        float2 v = vrow[r*64];
        float2 o;
        o.x = fmaxf(res[r].x, 0.f) + v.x;
        o.y = fmaxf(res[r].y, 0.f) + v.y;
        orow[r*64] = o;
    }
}

// ---------------------------------------------------------------------------
extern "C" void kernel_launch(void* const* d_in, const int* in_sizes, int n_in,
                              void* d_out, int out_size) {
    const float* inQ   = (const float*)d_in[0];
    const float* inK   = (const float*)d_in[1];
    const float* inV   = (const float*)d_in[2];
    const float* wq_v  = (const float*)d_in[3];
    const float* wq_g  = (const float*)d_in[4];
    const float* wk_v  = (const float*)d_in[5];
    const float* wk_g  = (const float*)d_in[6];
    const float* wv_v  = (const float*)d_in[7];
    const float* wv_g  = (const float*)d_in[8];
    const float* fc_v  = (const float*)d_in[9];
    const float* fc_g  = (const float*)d_in[10];
    const float* rel_k = (const float*)d_in[11];
    const float* rel_v = (const float*)d_in[12];
    const float* w1    = (const float*)d_in[13];
    const float* w2    = (const float*)d_in[14];
    const float* gamma = (const float*)d_in[15];
    const float* beta  = (const float*)d_in[16];

    float* out      = (float*)d_out;
    float* attn_out = out + (size_t)ROWS * D_;

    const int proj_smem = 3 * TP * L_ * D_ * (int)sizeof(float);   // 73728 B
    cudaFuncSetAttribute(proj_kernel, cudaFuncAttributeMaxDynamicSharedMemorySize, proj_smem);

    prep_kernel<<<5, 128>>>(wq_v, wq_g, wk_v, wk_g, wv_v, wv_g, fc_v, fc_g, rel_k, rel_v);
    proj_kernel<<<NBP, 256, proj_smem>>>(inQ, inK, inV);
    mid_kernel<<<BN, 128>>>(w1, w2, attn_out);
    stats_kernel<<<D_, 256>>>(gamma, beta);
    out_kernel<<<NBP, 256>>>(inV, out);
}

// round 5
// speedup vs baseline: 2.4472x; 1.6151x over previous
#include <cuda_runtime.h>
#include <math.h>

#define B_      32
#define N_      325
#define L_      12
#define D_      128
#define H_      8
#define DK      16
#define BN      (B_*N_)        // 10400
#define ROWS    (BN*L_)        // 124800
#define MAXREL  11
#define LL      (L_*L_)        // 144
#define HLL     (H_*LL)        // 1152
#define PITCH   132            // tf32 smem pitch (words): 4g+tig bank-unique
#define VP      20
#define MB      (ROWS/128)     // 975 row-blocks of 128

typedef unsigned int u32t;

// ---- static device scratch ----
__device__ __align__(16) u32t  g_Wfrag[4][D_*D_];   // tf32 weights in B-fragment order
__device__ __align__(16) float g_K2[LL*DK];
__device__ __align__(16) float g_V2[LL*DK];
__device__ __align__(16) float g_q[(size_t)ROWS*D_];
__device__ __align__(16) float g_k[(size_t)ROWS*D_];
__device__ __align__(16) float g_v[(size_t)ROWS*D_];
__device__ __align__(16) float g_ctx[(size_t)ROWS*D_];
__device__ __align__(16) float g_psum[D_*BN];
__device__ __align__(16) float g_psumsq[D_*BN];
__device__ float g_scale[D_];
__device__ float g_shift[D_];

__device__ __forceinline__ u32t to_tf32(float x) {
    u32t t; asm("cvt.rna.tf32.f32 %0, %1;" : "=r"(t) : "f"(x)); return t;
}
__device__ __forceinline__ void mma_tf32(float c[4], const u32t a[4], u32t b0, u32t b1) {
    asm volatile("mma.sync.aligned.m16n8k8.row.col.f32.tf32.tf32.f32 "
                 "{%0,%1,%2,%3}, {%4,%5,%6,%7}, {%8,%9}, {%0,%1,%2,%3};"
                 : "+f"(c[0]), "+f"(c[1]), "+f"(c[2]), "+f"(c[3])
                 : "r"(a[0]), "r"(a[1]), "r"(a[2]), "r"(a[3]), "r"(b0), "r"(b1));
}

// ---------------------------------------------------------------------------
// Kernel 1: weight-norm -> tf32 B-fragment layout; rel-position tables
// Wfrag element idx = ((kk*16 + nn)*64 + lane*2 + r):
//   k = kk*8 + (lane&3) + 4*r ; n = nn*8 + (lane>>2) ; value = tf32(W[n][k])
// ---------------------------------------------------------------------------
__global__ void prep_kernel(const float* __restrict__ wq_v, const float* __restrict__ wq_g,
                            const float* __restrict__ wk_v, const float* __restrict__ wk_g,
                            const float* __restrict__ wv_v, const float* __restrict__ wv_g,
                            const float* __restrict__ fc_v, const float* __restrict__ fc_g,
                            const float* __restrict__ rel_k, const float* __restrict__ rel_v) {
    int blk = blockIdx.x;
    if (blk < 4) {
        const float* v; const float* g;
        switch (blk) {
            case 0: v = wq_v; g = wq_g; break;
            case 1: v = wk_v; g = wk_g; break;
            case 2: v = wv_v; g = wv_g; break;
            default: v = fc_v; g = fc_g; break;
        }
        __shared__ float s_sc[D_];
        int r = threadIdx.x;           // 128 threads
        float s = 0.f;
        for (int d = 0; d < D_; d++) { float x = v[r*D_ + d]; s += x*x; }
        s_sc[r] = g[r] * rsqrtf(s);
        __syncthreads();
        for (int idx = threadIdx.x; idx < D_*D_; idx += 128) {
            int rr   = idx & 1;
            int lane = (idx >> 1) & 31;
            int nn   = (idx >> 6) & 15;
            int kk   = idx >> 10;
            int k = kk*8 + (lane & 3) + 4*rr;
            int n = nn*8 + (lane >> 2);
            g_Wfrag[blk][idx] = to_tf32(v[n*D_ + k] * s_sc[n]);
        }
    } else {
        for (int t = threadIdx.x; t < LL; t += blockDim.x) {
            int q = t / L_, k = t % L_;
            int dist = max(-MAXREL, min(MAXREL, k - q));
            int row = dist + MAXREL;
            for (int d = 0; d < DK; d++) {
                g_K2[t*DK + d] = rel_k[row*DK + d];
                g_V2[t*DK + d] = rel_v[row*DK + d];
            }
        }
    }
}

// ---------------------------------------------------------------------------
// 128x128x128 tf32 MMA tile. s_x: tf32, pitch PITCH. Warp (mw,nw): rows 32*mw,
// cols 64*nw. acc[mt][nn][4] covers (16 rows)x(8 cols) each.
// ---------------------------------------------------------------------------
__device__ __forceinline__ void mma_block(const u32t* __restrict__ s_x,
                                          const u32t* __restrict__ Wf,
                                          int lane, int mw, int nw,
                                          float acc[2][8][4]) {
    const int g = lane >> 2, tig = lane & 3;
    #pragma unroll
    for (int mt = 0; mt < 2; mt++)
        #pragma unroll
        for (int nn = 0; nn < 8; nn++)
            #pragma unroll
            for (int q = 0; q < 4; q++) acc[mt][nn][q] = 0.f;

    #pragma unroll 4
    for (int kk = 0; kk < 16; kk++) {
        u32t a[2][4];
        #pragma unroll
        for (int mt = 0; mt < 2; mt++) {
            const u32t* base = s_x + (mw*32 + mt*16 + g)*PITCH + kk*8 + tig;
            a[mt][0] = base[0];
            a[mt][1] = base[8*PITCH];
            a[mt][2] = base[4];
            a[mt][3] = base[8*PITCH + 4];
        }
        const u32t* bp = Wf + (kk*16 + nw*8)*64 + lane*2;
        #pragma unroll
        for (int nn = 0; nn < 8; nn++) {
            u32t b0 = bp[nn*64 + 0];
            u32t b1 = bp[nn*64 + 1];
            mma_tf32(acc[0][nn], a[0], b0, b1);
            mma_tf32(acc[1][nn], a[1], b0, b1);
        }
    }
}

// ---------------------------------------------------------------------------
// Kernel 2: QKV projections (tf32 MMA). grid = (MB, 3)
// ---------------------------------------------------------------------------
__global__ __launch_bounds__(256, 2) void proj_kernel(const float* __restrict__ inQ,
                                                      const float* __restrict__ inK,
                                                      const float* __restrict__ inV) {
    __shared__ __align__(16) u32t s_x[128*PITCH];
    const int tid = threadIdx.x;
    const int m = blockIdx.y;
    const float* src = (m == 0 ? inQ : (m == 1 ? inK : inV));
    float* dstg = (m == 0 ? g_q : (m == 1 ? g_k : g_v));
    const size_t base = (size_t)blockIdx.x * 128 * D_;

    const float4* s4 = (const float4*)(src + base);
    for (int i = tid; i < 128*32; i += 256) {
        float4 x = s4[i];
        int row = i >> 5, c4 = i & 31;
        uint4 t;
        t.x = to_tf32(x.x); t.y = to_tf32(x.y); t.z = to_tf32(x.z); t.w = to_tf32(x.w);
        ((uint4*)(s_x + row*PITCH))[c4] = t;
    }
    __syncthreads();

    const int lane = tid & 31, warp = tid >> 5;
    const int mw = warp & 3, nw = warp >> 2;
    const int g = lane >> 2, tig = lane & 3;
    float acc[2][8][4];
    mma_block(s_x, g_Wfrag[m], lane, mw, nw, acc);

    float* dst = dstg + base;
    #pragma unroll
    for (int mt = 0; mt < 2; mt++) {
        #pragma unroll
        for (int nn = 0; nn < 8; nn++) {
            int row = mw*32 + mt*16 + g;
            int col = nw*64 + nn*8 + 2*tig;
            *(float2*)(dst + (size_t)row*D_ + col)     = make_float2(acc[mt][nn][0], acc[mt][nn][1]);
            *(float2*)(dst + (size_t)(row+8)*D_ + col) = make_float2(acc[mt][nn][2], acc[mt][nn][3]);
        }
    }
}

// ---------------------------------------------------------------------------
// Kernel 3: attention middle, one (b,n) per block, 128 threads (unchanged R4)
// ---------------------------------------------------------------------------
__global__ __launch_bounds__(128) void mid_kernel(const float* __restrict__ w1,
                                                  const float* __restrict__ w2,
                                                  float* __restrict__ attn_out) {
    __shared__ __align__(16) float s_q[L_*PITCH];
    __shared__ __align__(16) float s_k[L_*PITCH];
    __shared__ __align__(16) float s_v[L_*PITCH];
    __shared__ __align__(16) float s_k2[LL*VP];
    __shared__ __align__(16) float s_v2[LL*VP];
    __shared__ float s_sc[HLL];
    __shared__ float s_at[HLL];
    __shared__ float s_at2[HLL];
    __shared__ float s_w1[64], s_w2[64];

    const int tid = threadIdx.x;
    const int bn  = blockIdx.x;

    if (tid < 64) { s_w1[tid] = w1[tid]; s_w2[tid] = w2[tid]; }

    const float4* gq = (const float4*)(g_q + (size_t)bn * (L_*D_));
    const float4* gk = (const float4*)(g_k + (size_t)bn * (L_*D_));
    const float4* gv = (const float4*)(g_v + (size_t)bn * (L_*D_));
    for (int i = tid; i < 384; i += 128) {
        int row = i >> 5, c4 = i & 31;
        ((float4*)s_q)[row*33 + c4] = gq[i];
        ((float4*)s_k)[row*33 + c4] = gk[i];
        ((float4*)s_v)[row*33 + c4] = gv[i];
    }
    for (int t = tid; t < LL; t += 128) {
        const float4* sk = (const float4*)(g_K2 + t*DK);
        const float4* sv = (const float4*)(g_V2 + t*DK);
        float4* dk = (float4*)(s_k2 + t*VP);
        float4* dv = (float4*)(s_v2 + t*VP);
        #pragma unroll
        for (int j = 0; j < 4; j++) { dk[j] = sk[j]; dv[j] = sv[j]; }
    }
    __syncthreads();

    for (int idx = tid; idx < HLL; idx += 128) {
        int h = idx / LL, rem = idx - h*LL;
        int i = rem / L_, j = rem - i*L_;
        const float4* qi = (const float4*)(s_q + i*PITCH + h*DK);
        const float4* kj = (const float4*)(s_k + j*PITCH + h*DK);
        const float4* k2 = (const float4*)(s_k2 + rem*VP);
        float s = 0.f;
        #pragma unroll
        for (int d4 = 0; d4 < 4; d4++) {
            float4 q4 = qi[d4], kk = kj[d4], r4 = k2[d4];
            s += q4.x*(kk.x+r4.x) + q4.y*(kk.y+r4.y) + q4.z*(kk.z+r4.z) + q4.w*(kk.w+r4.w);
        }
        s_sc[idx] = s * 0.25f;
    }
    __syncthreads();

    for (int idx = tid; idx < HLL; idx += 128) {
        int gh = idx / LL, rem = idx - gh*LL;
        const float* base = s_sc + rem;
        float s = 0.f;
        #pragma unroll
        for (int h = 0; h < H_; h++) s += base[h*LL] * s_w1[h*H_ + gh];
        s_at[idx] = (s > 0.f) ? s : 0.2f * s;
    }
    __syncthreads();

    if (tid < H_*L_) {
        float* row = s_at + tid * L_;
        float mx = row[0];
        #pragma unroll
        for (int j = 1; j < L_; j++) mx = fmaxf(mx, row[j]);
        float sum = 0.f;
        #pragma unroll
        for (int j = 0; j < L_; j++) { float e = __expf(row[j] - mx); row[j] = e; sum += e; }
        float inv = 1.f / sum;
        #pragma unroll
        for (int j = 0; j < L_; j++) row[j] *= inv;
    }
    __syncthreads();

    for (int idx = tid; idx < HLL; idx += 128) {
        int gh = idx / LL, rem = idx - gh*LL;
        const float* base = s_at + rem;
        float s = 0.f;
        #pragma unroll
        for (int h = 0; h < H_; h++) s += base[h*LL] * s_w2[h*H_ + gh];
        s_at2[idx] = s;
    }
    __syncthreads();

    for (int idx = tid; idx < HLL; idx += 128) {
        int i = idx / 96, hj = idx - i*96;
        int h = hj / L_, j = hj - h*L_;
        attn_out[(size_t)i * ((size_t)BN*96) + (size_t)bn*96 + hj] = s_at2[h*LL + i*L_ + j];
    }

    {
        const int c = tid;
        const int h = c >> 4, d = c & 15;
        float vj[12];
        #pragma unroll
        for (int j = 0; j < L_; j++) vj[j] = s_v[j*PITCH + c];
        const float* at = s_at2 + h*LL;
        float* ctxp = g_ctx + (size_t)bn * (L_*D_);
        float sum = 0.f, sq = 0.f;
        #pragma unroll
        for (int i = 0; i < L_; i++) {
            float acc = 0.f;
            #pragma unroll
            for (int j = 0; j < L_; j++)
                acc = fmaf(at[i*L_ + j], vj[j] + s_v2[(i*L_ + j)*VP + d], acc);
            ctxp[i*D_ + c] = acc;
            sum += acc;
            sq = fmaf(acc, acc, sq);
        }
        g_psum  [c*BN + bn] = sum;
        g_psumsq[c*BN + bn] = sq;
    }
}

// ---------------------------------------------------------------------------
// Kernel 4: finalize BN stats
// ---------------------------------------------------------------------------
__global__ void stats_kernel(const float* __restrict__ gamma, const float* __restrict__ beta) {
    const int c = blockIdx.x;
    __shared__ float sh[256], shq[256];
    float s = 0.f, ss = 0.f;
    for (int t = threadIdx.x; t < BN; t += 256) {
        s  += g_psum[c*BN + t];
        ss += g_psumsq[c*BN + t];
    }
    sh[threadIdx.x] = s; shq[threadIdx.x] = ss;
    __syncthreads();
    for (int st = 128; st > 0; st >>= 1) {
        if (threadIdx.x < st) {
            sh[threadIdx.x]  += sh[threadIdx.x + st];
            shq[threadIdx.x] += shq[threadIdx.x + st];
        }
        __syncthreads();
    }
    if (threadIdx.x == 0) {
        const float invN = 1.f / (float)ROWS;
        float mean = sh[0] * invN;
        float var  = shq[0] * invN - mean*mean;
        float sc = rsqrtf(var + 1e-5f) * gamma[c];
        g_scale[c] = sc;
        g_shift[c] = beta[c] - mean * sc;
    }
}

// ---------------------------------------------------------------------------
// Kernel 5: BN-apply + fc GEMM (tf32 MMA) + ReLU + residual. grid = MB
// ---------------------------------------------------------------------------
__global__ __launch_bounds__(256, 2) void out_kernel(const float* __restrict__ inV,
                                                     float* __restrict__ out) {
    __shared__ __align__(16) u32t s_x[128*PITCH];
    __shared__ float s_scale[D_], s_shift[D_];
    const int tid = threadIdx.x;
    const size_t base = (size_t)blockIdx.x * 128 * D_;

    if (tid < D_) { s_scale[tid] = g_scale[tid]; s_shift[tid] = g_shift[tid]; }
    __syncthreads();

    const float4* ctx4 = (const float4*)(g_ctx + base);
    const float4* sc4 = (const float4*)s_scale;
    const float4* sh4 = (const float4*)s_shift;
    for (int i = tid; i < 128*32; i += 256) {
        float4 x = ctx4[i];
        float4 sc = sc4[i & 31], sh = sh4[i & 31];
        int row = i >> 5, c4 = i & 31;
        uint4 t;
        t.x = to_tf32(x.x*sc.x + sh.x);
        t.y = to_tf32(x.y*sc.y + sh.y);
        t.z = to_tf32(x.z*sc.z + sh.z);
        t.w = to_tf32(x.w*sc.w + sh.w);
        ((uint4*)(s_x + row*PITCH))[c4] = t;
    }
    __syncthreads();

    const int lane = tid & 31, warp = tid >> 5;
    const int mw = warp & 3, nw = warp >> 2;
    const int g = lane >> 2, tig = lane & 3;
    float acc[2][8][4];
    mma_block(s_x, g_Wfrag[3], lane, mw, nw, acc);

    const float* vin = inV + base;
    float* dst = out + base;
    #pragma unroll
    for (int mt = 0; mt < 2; mt++) {
        #pragma unroll
        for (int nn = 0; nn < 8; nn++) {
            int row = mw*32 + mt*16 + g;
            int col = nw*64 + nn*8 + 2*tig;
            float2 v0 = *(const float2*)(vin + (size_t)row*D_ + col);
            float2 v1 = *(const float2*)(vin + (size_t)(row+8)*D_ + col);
            float2 o0, o1;
            o0.x = fmaxf(acc[mt][nn][0], 0.f) + v0.x;
            o0.y = fmaxf(acc[mt][nn][1], 0.f) + v0.y;
            o1.x = fmaxf(acc[mt][nn][2], 0.f) + v1.x;
            o1.y = fmaxf(acc[mt][nn][3], 0.f) + v1.y;
            *(float2*)(dst + (size_t)row*D_ + col)     = o0;
            *(float2*)(dst + (size_t)(row+8)*D_ + col) = o1;
        }
    }
}

// ---------------------------------------------------------------------------
extern "C" void kernel_launch(void* const* d_in, const int* in_sizes, int n_in,
                              void* d_out, int out_size) {
    const float* inQ   = (const float*)d_in[0];
    const float* inK   = (const float*)d_in[1];
    const float* inV   = (const float*)d_in[2];
    const float* wq_v  = (const float*)d_in[3];
    const float* wq_g  = (const float*)d_in[4];
    const float* wk_v  = (const float*)d_in[5];
    const float* wk_g  = (const float*)d_in[6];
    const float* wv_v  = (const float*)d_in[7];
    const float* wv_g  = (const float*)d_in[8];
    const float* fc_v  = (const float*)d_in[9];
    const float* fc_g  = (const float*)d_in[10];
    const float* rel_k = (const float*)d_in[11];
    const float* rel_v = (const float*)d_in[12];
    const float* w1    = (const float*)d_in[13];
    const float* w2    = (const float*)d_in[14];
    const float* gamma = (const float*)d_in[15];
    const float* beta  = (const float*)d_in[16];

    float* out      = (float*)d_out;
    float* attn_out = out + (size_t)ROWS * D_;

    prep_kernel<<<5, 128>>>(wq_v, wq_g, wk_v, wk_g, wv_v, wv_g, fc_v, fc_g, rel_k, rel_v);
    proj_kernel<<<dim3(MB, 3), 256>>>(inQ, inK, inV);
    mid_kernel<<<BN, 128>>>(w1, w2, attn_out);
    stats_kernel<<<D_, 256>>>(gamma, beta);
    out_kernel<<<MB, 256>>>(inV, out);
}

// round 6
// speedup vs baseline: 2.7579x; 1.1270x over previous
#include <cuda_runtime.h>
#include <math.h>

#define B_      32
#define N_      325
#define L_      12
#define D_      128
#define H_      8
#define DK      16
#define BN      (B_*N_)        // 10400
#define ROWS    (BN*L_)        // 124800
#define MAXREL  11
#define LL      (L_*L_)        // 144
#define HLL     (H_*LL)        // 1152
#define PITCH   132
#define TT      4              // (b,n) tiles per fused block
#define MROWS   (TT*L_)        // 48
#define NBF     (BN/TT)        // 2600
#define MB      (ROWS/128)     // 975 for out_kernel

typedef unsigned int u32t;

// ---- static device scratch ----
__device__ __align__(16) u32t  g_Wfrag[4][D_*D_];   // tf32 weights in B-fragment order
__device__ __align__(16) float g_K2[LL*DK];
__device__ __align__(16) float g_V2[LL*DK];
__device__ __align__(16) float g_ctx[(size_t)ROWS*D_];
__device__ __align__(16) float g_psum[D_*BN];
__device__ __align__(16) float g_psumsq[D_*BN];
__device__ float g_scale[D_];
__device__ float g_shift[D_];

__device__ __forceinline__ u32t to_tf32(float x) {
    u32t t; asm("cvt.rna.tf32.f32 %0, %1;" : "=r"(t) : "f"(x)); return t;
}
__device__ __forceinline__ void mma_tf32(float c[4], const u32t a[4], u32t b0, u32t b1) {
    asm volatile("mma.sync.aligned.m16n8k8.row.col.f32.tf32.tf32.f32 "
                 "{%0,%1,%2,%3}, {%4,%5,%6,%7}, {%8,%9}, {%0,%1,%2,%3};"
                 : "+f"(c[0]), "+f"(c[1]), "+f"(c[2]), "+f"(c[3])
                 : "r"(a[0]), "r"(a[1]), "r"(a[2]), "r"(a[3]), "r"(b0), "r"(b1));
}

// ---------------------------------------------------------------------------
// Kernel 1: weight-norm -> tf32 B-fragment layout; rel-position tables
// ---------------------------------------------------------------------------
__global__ void prep_kernel(const float* __restrict__ wq_v, const float* __restrict__ wq_g,
                            const float* __restrict__ wk_v, const float* __restrict__ wk_g,
                            const float* __restrict__ wv_v, const float* __restrict__ wv_g,
                            const float* __restrict__ fc_v, const float* __restrict__ fc_g,
                            const float* __restrict__ rel_k, const float* __restrict__ rel_v) {
    int blk = blockIdx.x;
    if (blk < 4) {
        const float* v; const float* g;
        switch (blk) {
            case 0: v = wq_v; g = wq_g; break;
            case 1: v = wk_v; g = wk_g; break;
            case 2: v = wv_v; g = wv_g; break;
            default: v = fc_v; g = fc_g; break;
        }
        __shared__ float s_sc[D_];
        int r = threadIdx.x;
        float s = 0.f;
        for (int d = 0; d < D_; d++) { float x = v[r*D_ + d]; s += x*x; }
        s_sc[r] = g[r] * rsqrtf(s);
        __syncthreads();
        for (int idx = threadIdx.x; idx < D_*D_; idx += 128) {
            int rr   = idx & 1;
            int lane = (idx >> 1) & 31;
            int nn   = (idx >> 6) & 15;
            int kk   = idx >> 10;
            int k = kk*8 + (lane & 3) + 4*rr;
            int n = nn*8 + (lane >> 2);
            g_Wfrag[blk][idx] = to_tf32(v[n*D_ + k] * s_sc[n]);
        }
    } else {
        for (int t = threadIdx.x; t < LL; t += blockDim.x) {
            int q = t / L_, k = t % L_;
            int dist = max(-MAXREL, min(MAXREL, k - q));
            int row = dist + MAXREL;
            for (int d = 0; d < DK; d++) {
                g_K2[t*DK + d] = rel_k[row*DK + d];
                g_V2[t*DK + d] = rel_v[row*DK + d];
            }
        }
    }
}

// ---------------------------------------------------------------------------
// 48x128x128 warp-MMA helpers (warps 0..5: mw = warp>>1 in 0..2, nw = warp&1)
// ---------------------------------------------------------------------------
__device__ __forceinline__ void mma_warp48(const u32t* __restrict__ s_x,
                                           const u32t* __restrict__ Wf,
                                           int mw, int nw, int lane, float acc[8][4]) {
    const int g = lane >> 2, tig = lane & 3;
    #pragma unroll
    for (int nn = 0; nn < 8; nn++)
        #pragma unroll
        for (int q = 0; q < 4; q++) acc[nn][q] = 0.f;
    #pragma unroll 4
    for (int kk = 0; kk < 16; kk++) {
        u32t a[4];
        const u32t* base = s_x + (mw*16 + g)*PITCH + kk*8 + tig;
        a[0] = base[0];
        a[1] = base[8*PITCH];
        a[2] = base[4];
        a[3] = base[8*PITCH + 4];
        const u32t* bp = Wf + (kk*16 + nw*8)*64 + lane*2;
        #pragma unroll
        for (int nn = 0; nn < 8; nn++)
            mma_tf32(acc[nn], a, bp[nn*64], bp[nn*64 + 1]);
    }
}
__device__ __forceinline__ void store_warp48(float* __restrict__ dst,
                                             int mw, int nw, int lane, const float acc[8][4]) {
    const int g = lane >> 2, tig = lane & 3;
    const int row = mw*16 + g;
    const int colb = nw*64 + 2*tig;
    #pragma unroll
    for (int nn = 0; nn < 8; nn++) {
        *(float2*)(dst + row*PITCH + colb + nn*8)         = make_float2(acc[nn][0], acc[nn][1]);
        *(float2*)(dst + (row+8)*PITCH + colb + nn*8)     = make_float2(acc[nn][2], acc[nn][3]);
    }
}

// ---------------------------------------------------------------------------
// Kernel 2: FUSED projections + attention middle. 4 (b,n) tiles per block.
// smem floats: A 6336 | B 6336 | C 6336 | s_at 4608 | k2 2304 | v2 2304 | w 128
// ---------------------------------------------------------------------------
__global__ __launch_bounds__(256, 2) void fused_kernel(const float* __restrict__ inQ,
                                                       const float* __restrict__ inK,
                                                       const float* __restrict__ inV,
                                                       const float* __restrict__ w1,
                                                       const float* __restrict__ w2,
                                                       float* __restrict__ attn_out) {
    extern __shared__ __align__(16) float sm[];
    float* sA   = sm;            // Q fp32 -> later s_at2
    float* sB   = sm + 6336;     // K fp32
    float* sC   = sm + 12672;    // staging tf32 -> V fp32 (in place)
    float* s_at = sm + 19008;    // 4608
    float* s_k2 = sm + 23616;    // 2304
    float* s_v2 = sm + 25920;    // 2304
    float* s_w1 = sm + 28224;    // 64
    float* s_w2 = sm + 28288;    // 64
    float* s_at2 = sA;

    const int tid  = threadIdx.x;
    const int lane = tid & 31, warp = tid >> 5;
    const int mw = warp >> 1, nw = warp & 1;    // valid for warp < 6
    const int bn0 = blockIdx.x * TT;
    const size_t gbase = (size_t)bn0 * (L_*D_);
    float acc[8][4];

    // ---- phase 0: stage Xq -> C (tf32) + tables + w1/w2 ----
    {
        const float4* s4 = (const float4*)(inQ + gbase);
        for (int i = tid; i < MROWS*32; i += 256) {
            float4 x = s4[i];
            int row = i >> 5, c4 = i & 31;
            uint4 t;
            t.x = to_tf32(x.x); t.y = to_tf32(x.y); t.z = to_tf32(x.z); t.w = to_tf32(x.w);
            ((uint4*)(sC + row*PITCH))[c4] = t;
        }
        for (int t = tid; t < LL; t += 256) {
            const float4* sk = (const float4*)(g_K2 + t*DK);
            const float4* sv = (const float4*)(g_V2 + t*DK);
            #pragma unroll
            for (int j = 0; j < 4; j++) {
                ((float4*)(s_k2 + t*DK))[j] = sk[j];
                ((float4*)(s_v2 + t*DK))[j] = sv[j];
            }
        }
        if (tid < 64) { s_w1[tid] = w1[tid]; s_w2[tid] = w2[tid]; }
    }
    __syncthreads();

    // ---- Q GEMM ----
    if (warp < 6) mma_warp48((const u32t*)sC, g_Wfrag[0], mw, nw, lane, acc);
    __syncthreads();
    if (warp < 6) store_warp48(sA, mw, nw, lane, acc);
    {   // stage Xk -> C
        const float4* s4 = (const float4*)(inK + gbase);
        for (int i = tid; i < MROWS*32; i += 256) {
            float4 x = s4[i];
            int row = i >> 5, c4 = i & 31;
            uint4 t;
            t.x = to_tf32(x.x); t.y = to_tf32(x.y); t.z = to_tf32(x.z); t.w = to_tf32(x.w);
            ((uint4*)(sC + row*PITCH))[c4] = t;
        }
    }
    __syncthreads();

    // ---- K GEMM ----
    if (warp < 6) mma_warp48((const u32t*)sC, g_Wfrag[1], mw, nw, lane, acc);
    __syncthreads();
    if (warp < 6) store_warp48(sB, mw, nw, lane, acc);
    {   // stage Xv -> C
        const float4* s4 = (const float4*)(inV + gbase);
        for (int i = tid; i < MROWS*32; i += 256) {
            float4 x = s4[i];
            int row = i >> 5, c4 = i & 31;
            uint4 t;
            t.x = to_tf32(x.x); t.y = to_tf32(x.y); t.z = to_tf32(x.z); t.w = to_tf32(x.w);
            ((uint4*)(sC + row*PITCH))[c4] = t;
        }
    }
    __syncthreads();

    // ---- V GEMM (in-place into C; reg-buffered across sync) ----
    if (warp < 6) mma_warp48((const u32t*)sC, g_Wfrag[2], mw, nw, lane, acc);
    __syncthreads();
    if (warp < 6) store_warp48(sC, mw, nw, lane, acc);
    __syncthreads();

    // ---- scores + w1 mix + leaky relu (per item: all 8 heads in regs) ----
    for (int idx = tid; idx < TT*LL; idx += 256) {
        int t = idx / LL, rem = idx - t*LL;
        int i = rem / L_, j = rem - i*L_;
        const float* qrow = sA + (t*L_ + i)*PITCH;
        const float* krow = sB + (t*L_ + j)*PITCH;
        const float4* k2 = (const float4*)(s_k2 + rem*DK);
        float4 r0 = k2[0], r1 = k2[1], r2 = k2[2], r3 = k2[3];
        float sc[H_];
        #pragma unroll
        for (int h = 0; h < H_; h++) {
            const float4* q4 = (const float4*)(qrow + h*DK);
            const float4* k4 = (const float4*)(krow + h*DK);
            float4 q0 = q4[0], q1 = q4[1], q2 = q4[2], q3 = q4[3];
            float4 k0 = k4[0], k1 = k4[1], k2v = k4[2], k3 = k4[3];
            float s = 0.f;
            s += q0.x*(k0.x+r0.x) + q0.y*(k0.y+r0.y) + q0.z*(k0.z+r0.z) + q0.w*(k0.w+r0.w);
            s += q1.x*(k1.x+r1.x) + q1.y*(k1.y+r1.y) + q1.z*(k1.z+r1.z) + q1.w*(k1.w+r1.w);
            s += q2.x*(k2v.x+r2.x) + q2.y*(k2v.y+r2.y) + q2.z*(k2v.z+r2.z) + q2.w*(k2v.w+r2.w);
            s += q3.x*(k3.x+r3.x) + q3.y*(k3.y+r3.y) + q3.z*(k3.z+r3.z) + q3.w*(k3.w+r3.w);
            sc[h] = s * 0.25f;
        }
        #pragma unroll
        for (int g = 0; g < H_; g++) {
            float s = 0.f;
            #pragma unroll
            for (int h = 0; h < H_; h++) s += sc[h] * s_w1[h*H_ + g];
            s_at[t*HLL + g*LL + rem] = (s > 0.f) ? s : 0.2f * s;
        }
    }
    __syncthreads();

    // ---- softmax over k: TT*96 rows of 12 ----
    for (int rowid = tid; rowid < TT*H_*L_; rowid += 256) {
        float* row = s_at + rowid * L_;
        float mx = row[0];
        #pragma unroll
        for (int j = 1; j < L_; j++) mx = fmaxf(mx, row[j]);
        float sum = 0.f;
        #pragma unroll
        for (int j = 0; j < L_; j++) { float e = __expf(row[j] - mx); row[j] = e; sum += e; }
        float inv = 1.f / sum;
        #pragma unroll
        for (int j = 0; j < L_; j++) row[j] *= inv;
    }
    __syncthreads();

    // ---- w2 mix -> s_at2 (A region; Q dead) + attn_ret write ----
    for (int idx = tid; idx < TT*LL; idx += 256) {
        int t = idx / LL, rem = idx - t*LL;
        int i = rem / L_, j = rem - i*L_;
        float a[H_];
        #pragma unroll
        for (int h = 0; h < H_; h++) a[h] = s_at[t*HLL + h*LL + rem];
        #pragma unroll
        for (int g = 0; g < H_; g++) {
            float s = 0.f;
            #pragma unroll
            for (int h = 0; h < H_; h++) s += a[h] * s_w2[h*H_ + g];
            s_at2[t*HLL + g*LL + rem] = s;
            attn_out[(size_t)i * ((size_t)BN*96) + (size_t)(bn0+t)*96 + g*L_ + j] = s;
        }
    }
    __syncthreads();

    // ---- context + BN partials: 2 tiles per 128-thread half ----
    {
        const int c = tid & 127;
        const int h = c >> 4, d = c & 15;
        #pragma unroll
        for (int tt = 0; tt < 2; tt++) {
            const int t = (tid >> 7) + 2*tt;
            float vj[L_];
            #pragma unroll
            for (int j = 0; j < L_; j++) vj[j] = sC[(t*L_ + j)*PITCH + c];
            const float* at = s_at2 + t*HLL + h*LL;
            float* ctxp = g_ctx + (size_t)(bn0 + t) * (L_*D_);
            float sum = 0.f, sq = 0.f;
            #pragma unroll
            for (int i = 0; i < L_; i++) {
                float a2 = 0.f;
                #pragma unroll
                for (int j = 0; j < L_; j++)
                    a2 = fmaf(at[i*L_ + j], vj[j] + s_v2[(i*L_ + j)*DK + d], a2);
                ctxp[i*D_ + c] = a2;
                sum += a2;
                sq = fmaf(a2, a2, sq);
            }
            g_psum  [c*BN + bn0 + t] = sum;
            g_psumsq[c*BN + bn0 + t] = sq;
        }
    }
}

// ---------------------------------------------------------------------------
// Kernel 3: finalize BN stats
// ---------------------------------------------------------------------------
__global__ void stats_kernel(const float* __restrict__ gamma, const float* __restrict__ beta) {
    const int c = blockIdx.x;
    __shared__ float sh[256], shq[256];
    float s = 0.f, ss = 0.f;
    for (int t = threadIdx.x; t < BN; t += 256) {
        s  += g_psum[c*BN + t];
        ss += g_psumsq[c*BN + t];
    }
    sh[threadIdx.x] = s; shq[threadIdx.x] = ss;
    __syncthreads();
    for (int st = 128; st > 0; st >>= 1) {
        if (threadIdx.x < st) {
            sh[threadIdx.x]  += sh[threadIdx.x + st];
            shq[threadIdx.x] += shq[threadIdx.x + st];
        }
        __syncthreads();
    }
    if (threadIdx.x == 0) {
        const float invN = 1.f / (float)ROWS;
        float mean = sh[0] * invN;
        float var  = shq[0] * invN - mean*mean;
        float sc = rsqrtf(var + 1e-5f) * gamma[c];
        g_scale[c] = sc;
        g_shift[c] = beta[c] - mean * sc;
    }
}

// ---------------------------------------------------------------------------
// 128x128x128 tf32 MMA tile for out_kernel (8 warps, m32n64 each)
// ---------------------------------------------------------------------------
__device__ __forceinline__ void mma_block(const u32t* __restrict__ s_x,
                                          const u32t* __restrict__ Wf,
                                          int lane, int mw, int nw,
                                          float acc[2][8][4]) {
    const int g = lane >> 2, tig = lane & 3;
    #pragma unroll
    for (int mt = 0; mt < 2; mt++)
        #pragma unroll
        for (int nn = 0; nn < 8; nn++)
            #pragma unroll
            for (int q = 0; q < 4; q++) acc[mt][nn][q] = 0.f;

    #pragma unroll 4
    for (int kk = 0; kk < 16; kk++) {
        u32t a[2][4];
        #pragma unroll
        for (int mt = 0; mt < 2; mt++) {
            const u32t* base = s_x + (mw*32 + mt*16 + g)*PITCH + kk*8 + tig;
            a[mt][0] = base[0];
            a[mt][1] = base[8*PITCH];
            a[mt][2] = base[4];
            a[mt][3] = base[8*PITCH + 4];
        }
        const u32t* bp = Wf + (kk*16 + nw*8)*64 + lane*2;
        #pragma unroll
        for (int nn = 0; nn < 8; nn++) {
            u32t b0 = bp[nn*64 + 0];
            u32t b1 = bp[nn*64 + 1];
            mma_tf32(acc[0][nn], a[0], b0, b1);
            mma_tf32(acc[1][nn], a[1], b0, b1);
        }
    }
}

// ---------------------------------------------------------------------------
// Kernel 4: BN-apply + fc GEMM (tf32 MMA) + ReLU + residual. grid = MB
// ---------------------------------------------------------------------------
__global__ __launch_bounds__(256, 2) void out_kernel(const float* __restrict__ inV,
                                                     float* __restrict__ out) {
    __shared__ __align__(16) u32t s_x[128*PITCH];
    __shared__ float s_scale[D_], s_shift[D_];
    const int tid = threadIdx.x;
    const size_t base = (size_t)blockIdx.x * 128 * D_;

    if (tid < D_) { s_scale[tid] = g_scale[tid]; s_shift[tid] = g_shift[tid]; }
    __syncthreads();

    const float4* ctx4 = (const float4*)(g_ctx + base);
    const float4* sc4 = (const float4*)s_scale;
    const float4* sh4 = (const float4*)s_shift;
    for (int i = tid; i < 128*32; i += 256) {
        float4 x = ctx4[i];
        float4 sc = sc4[i & 31], sh = sh4[i & 31];
        int row = i >> 5, c4 = i & 31;
        uint4 t;
        t.x = to_tf32(x.x*sc.x + sh.x);
        t.y = to_tf32(x.y*sc.y + sh.y);
        t.z = to_tf32(x.z*sc.z + sh.z);
        t.w = to_tf32(x.w*sc.w + sh.w);
        ((uint4*)(s_x + row*PITCH))[c4] = t;
    }
    __syncthreads();

    const int lane = tid & 31, warp = tid >> 5;
    const int mw = warp & 3, nw = warp >> 2;
    const int g = lane >> 2, tig = lane & 3;
    float acc[2][8][4];
    mma_block(s_x, g_Wfrag[3], lane, mw, nw, acc);

    const float* vin = inV + base;
    float* dst = out + base;
    #pragma unroll
    for (int mt = 0; mt < 2; mt++) {
        #pragma unroll
        for (int nn = 0; nn < 8; nn++) {
            int row = mw*32 + mt*16 + g;
            int col = nw*64 + nn*8 + 2*tig;
            float2 v0 = *(const float2*)(vin + (size_t)row*D_ + col);
            float2 v1 = *(const float2*)(vin + (size_t)(row+8)*D_ + col);
            float2 o0, o1;
            o0.x = fmaxf(acc[mt][nn][0], 0.f) + v0.x;
            o0.y = fmaxf(acc[mt][nn][1], 0.f) + v0.y;
            o1.x = fmaxf(acc[mt][nn][2], 0.f) + v1.x;
            o1.y = fmaxf(acc[mt][nn][3], 0.f) + v1.y;
            *(float2*)(dst + (size_t)row*D_ + col)     = o0;
            *(float2*)(dst + (size_t)(row+8)*D_ + col) = o1;
        }
    }
}

// ---------------------------------------------------------------------------
extern "C" void kernel_launch(void* const* d_in, const int* in_sizes, int n_in,
                              void* d_out, int out_size) {
    const float* inQ   = (const float*)d_in[0];
    const float* inK   = (const float*)d_in[1];
    const float* inV   = (const float*)d_in[2];
    const float* wq_v  = (const float*)d_in[3];
    const float* wq_g  = (const float*)d_in[4];
    const float* wk_v  = (const float*)d_in[5];
    const float* wk_g  = (const float*)d_in[6];
    const float* wv_v  = (const float*)d_in[7];
    const float* wv_g  = (const float*)d_in[8];
    const float* fc_v  = (const float*)d_in[9];
    const float* fc_g  = (const float*)d_in[10];
    const float* rel_k = (const float*)d_in[11];
    const float* rel_v = (const float*)d_in[12];
    const float* w1    = (const float*)d_in[13];
    const float* w2    = (const float*)d_in[14];
    const float* gamma = (const float*)d_in[15];
    const float* beta  = (const float*)d_in[16];

    float* out      = (float*)d_out;
    float* attn_out = out + (size_t)ROWS * D_;

    const int fused_smem = 28352 * (int)sizeof(float);   // 113,408 B
    cudaFuncSetAttribute(fused_kernel, cudaFuncAttributeMaxDynamicSharedMemorySize, fused_smem);

    prep_kernel<<<5, 128>>>(wq_v, wq_g, wk_v, wk_g, wv_v, wv_g, fc_v, fc_g, rel_k, rel_v);
    fused_kernel<<<NBF, 256, fused_smem>>>(inQ, inK, inV, w1, w2, attn_out);
    stats_kernel<<<D_, 256>>>(gamma, beta);
    out_kernel<<<MB, 256>>>(inV, out);
}

// round 7
// speedup vs baseline: 2.9014x; 1.0520x over previous
#include <cuda_runtime.h>
#include <math.h>

#define B_      32
#define N_      325
#define L_      12
#define D_      128
#define H_      8
#define DK      16
#define BN      (B_*N_)        // 10400
#define ROWS    (BN*L_)        // 124800
#define MAXREL  11
#define LL      (L_*L_)        // 144
#define HLL     (H_*LL)        // 1152
#define PITCH   132
#define TT      4              // (b,n) tiles per fused block
#define MROWS   (TT*L_)        // 48
#define NBF     (BN/TT)        // 2600
#define MO      64             // out_kernel row-tile
#define NBO     (ROWS/MO)      // 1950

typedef unsigned int u32t;

// ---- static device scratch ----
__device__ __align__(16) u32t  g_Wfrag[4][D_*D_];   // tf32 weights in B-fragment order
__device__ __align__(16) float g_K2[LL*DK];
__device__ __align__(16) float g_V2[LL*DK];
__device__ __align__(16) float g_ctx[(size_t)ROWS*D_];
__device__ __align__(16) float g_psum[D_*BN];
__device__ __align__(16) float g_psumsq[D_*BN];
__device__ float g_scale[D_];
__device__ float g_shift[D_];

__device__ __forceinline__ u32t to_tf32(float x) {
    u32t t; asm("cvt.rna.tf32.f32 %0, %1;" : "=r"(t) : "f"(x)); return t;
}
__device__ __forceinline__ void mma_tf32(float c[4], const u32t a[4], u32t b0, u32t b1) {
    asm volatile("mma.sync.aligned.m16n8k8.row.col.f32.tf32.tf32.f32 "
                 "{%0,%1,%2,%3}, {%4,%5,%6,%7}, {%8,%9}, {%0,%1,%2,%3};"
                 : "+f"(c[0]), "+f"(c[1]), "+f"(c[2]), "+f"(c[3])
                 : "r"(a[0]), "r"(a[1]), "r"(a[2]), "r"(a[3]), "r"(b0), "r"(b1));
}

// ---------------------------------------------------------------------------
// Kernel 1: weight-norm -> tf32 B-fragment layout; rel-position tables
// ---------------------------------------------------------------------------
__global__ void prep_kernel(const float* __restrict__ wq_v, const float* __restrict__ wq_g,
                            const float* __restrict__ wk_v, const float* __restrict__ wk_g,
                            const float* __restrict__ wv_v, const float* __restrict__ wv_g,
                            const float* __restrict__ fc_v, const float* __restrict__ fc_g,
                            const float* __restrict__ rel_k, const float* __restrict__ rel_v) {
    int blk = blockIdx.x;
    if (blk < 4) {
        const float* v; const float* g;
        switch (blk) {
            case 0: v = wq_v; g = wq_g; break;
            case 1: v = wk_v; g = wk_g; break;
            case 2: v = wv_v; g = wv_g; break;
            default: v = fc_v; g = fc_g; break;
        }
        __shared__ float s_sc[D_];
        int r = threadIdx.x;
        float s = 0.f;
        for (int d = 0; d < D_; d++) { float x = v[r*D_ + d]; s += x*x; }
        s_sc[r] = g[r] * rsqrtf(s);
        __syncthreads();
        for (int idx = threadIdx.x; idx < D_*D_; idx += 128) {
            int rr   = idx & 1;
            int lane = (idx >> 1) & 31;
            int nn   = (idx >> 6) & 15;
            int kk   = idx >> 10;
            int k = kk*8 + (lane & 3) + 4*rr;
            int n = nn*8 + (lane >> 2);
            g_Wfrag[blk][idx] = to_tf32(v[n*D_ + k] * s_sc[n]);
        }
    } else {
        for (int t = threadIdx.x; t < LL; t += blockDim.x) {
            int q = t / L_, k = t % L_;
            int dist = max(-MAXREL, min(MAXREL, k - q));
            int row = dist + MAXREL;
            for (int d = 0; d < DK; d++) {
                g_K2[t*DK + d] = rel_k[row*DK + d];
                g_V2[t*DK + d] = rel_v[row*DK + d];
            }
        }
    }
}

// ---------------------------------------------------------------------------
// m16n64 warp-MMA over K=128 from pitched tf32 smem (row = mw*16+g .. +8)
// ---------------------------------------------------------------------------
__device__ __forceinline__ void mma_warp(const u32t* __restrict__ s_x,
                                         const u32t* __restrict__ Wf,
                                         int mw, int nw, int lane, float acc[8][4]) {
    const int g = lane >> 2, tig = lane & 3;
    #pragma unroll
    for (int nn = 0; nn < 8; nn++)
        #pragma unroll
        for (int q = 0; q < 4; q++) acc[nn][q] = 0.f;
    #pragma unroll 4
    for (int kk = 0; kk < 16; kk++) {
        u32t a[4];
        const u32t* base = s_x + (mw*16 + g)*PITCH + kk*8 + tig;
        a[0] = base[0];
        a[1] = base[8*PITCH];
        a[2] = base[4];
        a[3] = base[8*PITCH + 4];
        const u32t* bp = Wf + (kk*16 + nw*8)*64 + lane*2;
        #pragma unroll
        for (int nn = 0; nn < 8; nn++)
            mma_tf32(acc[nn], a, bp[nn*64], bp[nn*64 + 1]);
    }
}
__device__ __forceinline__ void store_warp(float* __restrict__ dst,
                                           int mw, int nw, int lane, const float acc[8][4]) {
    const int g = lane >> 2, tig = lane & 3;
    const int row = mw*16 + g;
    const int colb = nw*64 + 2*tig;
    #pragma unroll
    for (int nn = 0; nn < 8; nn++) {
        *(float2*)(dst + row*PITCH + colb + nn*8)     = make_float2(acc[nn][0], acc[nn][1]);
        *(float2*)(dst + (row+8)*PITCH + colb + nn*8) = make_float2(acc[nn][2], acc[nn][3]);
    }
}

__device__ __forceinline__ void stage_tf32(const float* __restrict__ src, float* __restrict__ dst,
                                           int tid) {
    const float4* s4 = (const float4*)src;
    for (int i = tid; i < MROWS*32; i += 256) {
        float4 x = s4[i];
        int row = i >> 5, c4 = i & 31;
        uint4 t;
        t.x = to_tf32(x.x); t.y = to_tf32(x.y); t.z = to_tf32(x.z); t.w = to_tf32(x.w);
        ((uint4*)((u32t*)dst + row*PITCH))[c4] = t;
    }
}

// ---------------------------------------------------------------------------
// Kernel 2: FUSED projections + attention middle. 4 (b,n) tiles per block.
// ---------------------------------------------------------------------------
__global__ __launch_bounds__(256, 2) void fused_kernel(const float* __restrict__ inQ,
                                                       const float* __restrict__ inK,
                                                       const float* __restrict__ inV,
                                                       const float* __restrict__ w1,
                                                       const float* __restrict__ w2,
                                                       float* __restrict__ attn_out) {
    extern __shared__ __align__(16) float sm[];
    float* sA   = sm;            // Xq tf32 -> Q fp32 -> s_at2
    float* sB   = sm + 6336;     // Xk tf32 -> K fp32
    float* sC   = sm + 12672;    // Xv tf32 -> V fp32
    float* s_at = sm + 19008;    // 4608
    float* s_k2 = sm + 23616;    // 2304
    float* s_v2 = sm + 25920;    // 2304
    float* s_w1 = sm + 28224;    // 64
    float* s_w2 = sm + 28288;    // 64
    float* s_at2 = sA;

    const int tid  = threadIdx.x;
    const int lane = tid & 31, warp = tid >> 5;
    const int mw = warp >> 1, nw = warp & 1;    // valid for warp < 6
    const int bn0 = blockIdx.x * TT;
    const size_t gbase = (size_t)bn0 * (L_*D_);
    float acc[8][4];

    // ---- S0: stage all three inputs + tables ----
    stage_tf32(inQ + gbase, sA, tid);
    stage_tf32(inK + gbase, sB, tid);
    stage_tf32(inV + gbase, sC, tid);
    for (int t = tid; t < LL; t += 256) {
        const float4* sk = (const float4*)(g_K2 + t*DK);
        const float4* sv = (const float4*)(g_V2 + t*DK);
        #pragma unroll
        for (int j = 0; j < 4; j++) {
            ((float4*)(s_k2 + t*DK))[j] = sk[j];
            ((float4*)(s_v2 + t*DK))[j] = sv[j];
        }
    }
    if (tid < 64) { s_w1[tid] = w1[tid]; s_w2[tid] = w2[tid]; }
    __syncthreads();

    // ---- Q GEMM (in-place A) ----
    if (warp < 6) mma_warp((const u32t*)sA, g_Wfrag[0], mw, nw, lane, acc);
    __syncthreads();
    if (warp < 6) {
        store_warp(sA, mw, nw, lane, acc);                    // write A
        mma_warp((const u32t*)sB, g_Wfrag[1], mw, nw, lane, acc);  // read B (independent)
    }
    __syncthreads();
    if (warp < 6) {
        store_warp(sB, mw, nw, lane, acc);
        mma_warp((const u32t*)sC, g_Wfrag[2], mw, nw, lane, acc);
    }
    __syncthreads();
    if (warp < 6) store_warp(sC, mw, nw, lane, acc);
    __syncthreads();

    // ---- scores + w1 mix + leaky relu ----
    for (int idx = tid; idx < TT*LL; idx += 256) {
        int t = idx / LL, rem = idx - t*LL;
        int i = rem / L_, j = rem - i*L_;
        const float* qrow = sA + (t*L_ + i)*PITCH;
        const float* krow = sB + (t*L_ + j)*PITCH;
        const float4* k2 = (const float4*)(s_k2 + rem*DK);
        float4 r0 = k2[0], r1 = k2[1], r2 = k2[2], r3 = k2[3];
        float sc[H_];
        #pragma unroll
        for (int h = 0; h < H_; h++) {
            const float4* q4 = (const float4*)(qrow + h*DK);
            const float4* k4 = (const float4*)(krow + h*DK);
            float4 q0 = q4[0], q1 = q4[1], q2 = q4[2], q3 = q4[3];
            float4 k0 = k4[0], k1 = k4[1], k2v = k4[2], k3 = k4[3];
            float s = 0.f;
            s += q0.x*(k0.x+r0.x) + q0.y*(k0.y+r0.y) + q0.z*(k0.z+r0.z) + q0.w*(k0.w+r0.w);
            s += q1.x*(k1.x+r1.x) + q1.y*(k1.y+r1.y) + q1.z*(k1.z+r1.z) + q1.w*(k1.w+r1.w);
            s += q2.x*(k2v.x+r2.x) + q2.y*(k2v.y+r2.y) + q2.z*(k2v.z+r2.z) + q2.w*(k2v.w+r2.w);
            s += q3.x*(k3.x+r3.x) + q3.y*(k3.y+r3.y) + q3.z*(k3.z+r3.z) + q3.w*(k3.w+r3.w);
            sc[h] = s * 0.25f;
        }
        #pragma unroll
        for (int g = 0; g < H_; g++) {
            float s = 0.f;
            #pragma unroll
            for (int h = 0; h < H_; h++) s += sc[h] * s_w1[h*H_ + g];
            s_at[t*HLL + g*LL + rem] = (s > 0.f) ? s : 0.2f * s;
        }
    }
    __syncthreads();

    // ---- softmax over k: TT*96 rows of 12 ----
    for (int rowid = tid; rowid < TT*H_*L_; rowid += 256) {
        float* row = s_at + rowid * L_;
        float mx = row[0];
        #pragma unroll
        for (int j = 1; j < L_; j++) mx = fmaxf(mx, row[j]);
        float sum = 0.f;
        #pragma unroll
        for (int j = 0; j < L_; j++) { float e = __expf(row[j] - mx); row[j] = e; sum += e; }
        float inv = 1.f / sum;
        #pragma unroll
        for (int j = 0; j < L_; j++) row[j] *= inv;
    }
    __syncthreads();

    // ---- w2 mix -> s_at2 (A region; Q dead) + attn_ret write ----
    for (int idx = tid; idx < TT*LL; idx += 256) {
        int t = idx / LL, rem = idx - t*LL;
        int i = rem / L_, j = rem - i*L_;
        float a[H_];
        #pragma unroll
        for (int h = 0; h < H_; h++) a[h] = s_at[t*HLL + h*LL + rem];
        #pragma unroll
        for (int g = 0; g < H_; g++) {
            float s = 0.f;
            #pragma unroll
            for (int h = 0; h < H_; h++) s += a[h] * s_w2[h*H_ + g];
            s_at2[t*HLL + g*LL + rem] = s;
            attn_out[(size_t)i * ((size_t)BN*96) + (size_t)(bn0+t)*96 + g*L_ + j] = s;
        }
    }
    __syncthreads();

    // ---- context + BN partials ----
    {
        const int c = tid & 127;
        const int h = c >> 4, d = c & 15;
        #pragma unroll
        for (int tt = 0; tt < 2; tt++) {
            const int t = (tid >> 7) + 2*tt;
            float vj[L_];
            #pragma unroll
            for (int j = 0; j < L_; j++) vj[j] = sC[(t*L_ + j)*PITCH + c];
            const float* at = s_at2 + t*HLL + h*LL;
            float* ctxp = g_ctx + (size_t)(bn0 + t) * (L_*D_);
            float sum = 0.f, sq = 0.f;
            #pragma unroll
            for (int i = 0; i < L_; i++) {
                float a2 = 0.f;
                #pragma unroll
                for (int j = 0; j < L_; j++)
                    a2 = fmaf(at[i*L_ + j], vj[j] + s_v2[(i*L_ + j)*DK + d], a2);
                ctxp[i*D_ + c] = a2;
                sum += a2;
                sq = fmaf(a2, a2, sq);
            }
            g_psum  [c*BN + bn0 + t] = sum;
            g_psumsq[c*BN + bn0 + t] = sq;
        }
    }
}

// ---------------------------------------------------------------------------
// Kernel 3: finalize BN stats
// ---------------------------------------------------------------------------
__global__ void stats_kernel(const float* __restrict__ gamma, const float* __restrict__ beta) {
    const int c = blockIdx.x;
    __shared__ float sh[256], shq[256];
    float s = 0.f, ss = 0.f;
    for (int t = threadIdx.x; t < BN; t += 256) {
        s  += g_psum[c*BN + t];
        ss += g_psumsq[c*BN + t];
    }
    sh[threadIdx.x] = s; shq[threadIdx.x] = ss;
    __syncthreads();
    for (int st = 128; st > 0; st >>= 1) {
        if (threadIdx.x < st) {
            sh[threadIdx.x]  += sh[threadIdx.x + st];
            shq[threadIdx.x] += shq[threadIdx.x + st];
        }
        __syncthreads();
    }
    if (threadIdx.x == 0) {
        const float invN = 1.f / (float)ROWS;
        float mean = sh[0] * invN;
        float var  = shq[0] * invN - mean*mean;
        float sc = rsqrtf(var + 1e-5f) * gamma[c];
        g_scale[c] = sc;
        g_shift[c] = beta[c] - mean * sc;
    }
}

// ---------------------------------------------------------------------------
// Kernel 4: BN-apply + fc GEMM + ReLU + residual. M=64 tiles, grid=NBO.
// 8 warps: mw = warp&3 (m16), nw = warp>>2 (n64).
// ---------------------------------------------------------------------------
__global__ __launch_bounds__(256, 3) void out_kernel(const float* __restrict__ inV,
                                                     float* __restrict__ out) {
    __shared__ __align__(16) u32t s_x[MO*PITCH];
    __shared__ float s_scale[D_], s_shift[D_];
    const int tid = threadIdx.x;
    const size_t base = (size_t)blockIdx.x * MO * D_;

    if (tid < D_) { s_scale[tid] = g_scale[tid]; s_shift[tid] = g_shift[tid]; }
    __syncthreads();

    const float4* ctx4 = (const float4*)(g_ctx + base);
    const float4* sc4 = (const float4*)s_scale;
    const float4* sh4 = (const float4*)s_shift;
    for (int i = tid; i < MO*32; i += 256) {
        float4 x = ctx4[i];
        float4 sc = sc4[i & 31], sh = sh4[i & 31];
        int row = i >> 5, c4 = i & 31;
        uint4 t;
        t.x = to_tf32(x.x*sc.x + sh.x);
        t.y = to_tf32(x.y*sc.y + sh.y);
        t.z = to_tf32(x.z*sc.z + sh.z);
        t.w = to_tf32(x.w*sc.w + sh.w);
        ((uint4*)(s_x + row*PITCH))[c4] = t;
    }
    __syncthreads();

    const int lane = tid & 31, warp = tid >> 5;
    const int mw = warp & 3, nw = warp >> 2;
    const int g = lane >> 2, tig = lane & 3;
    float acc[8][4];
    mma_warp(s_x, g_Wfrag[3], mw, nw, lane, acc);

    const float* vin = inV + base;
    float* dst = out + base;
    const int row = mw*16 + g;
    const int colb = nw*64 + 2*tig;
    #pragma unroll
    for (int nn = 0; nn < 8; nn++) {
        int col = colb + nn*8;
        float2 v0 = *(const float2*)(vin + (size_t)row*D_ + col);
        float2 v1 = *(const float2*)(vin + (size_t)(row+8)*D_ + col);
        float2 o0, o1;
        o0.x = fmaxf(acc[nn][0], 0.f) + v0.x;
        o0.y = fmaxf(acc[nn][1], 0.f) + v0.y;
        o1.x = fmaxf(acc[nn][2], 0.f) + v1.x;
        o1.y = fmaxf(acc[nn][3], 0.f) + v1.y;
        *(float2*)(dst + (size_t)row*D_ + col)     = o0;
        *(float2*)(dst + (size_t)(row+8)*D_ + col) = o1;
    }
}

// ---------------------------------------------------------------------------
extern "C" void kernel_launch(void* const* d_in, const int* in_sizes, int n_in,
                              void* d_out, int out_size) {
    const float* inQ   = (const float*)d_in[0];
    const float* inK   = (const float*)d_in[1];
    const float* inV   = (const float*)d_in[2];
    const float* wq_v  = (const float*)d_in[3];
    const float* wq_g  = (const float*)d_in[4];
    const float* wk_v  = (const float*)d_in[5];
    const float* wk_g  = (const float*)d_in[6];
    const float* wv_v  = (const float*)d_in[7];
    const float* wv_g  = (const float*)d_in[8];
    const float* fc_v  = (const float*)d_in[9];
    const float* fc_g  = (const float*)d_in[10];
    const float* rel_k = (const float*)d_in[11];
    const float* rel_v = (const float*)d_in[12];
    const float* w1    = (const float*)d_in[13];
    const float* w2    = (const float*)d_in[14];
    const float* gamma = (const float*)d_in[15];
    const float* beta  = (const float*)d_in[16];

    float* out      = (float*)d_out;
    float* attn_out = out + (size_t)ROWS * D_;

    const int fused_smem = 28352 * (int)sizeof(float);   // 113,408 B
    cudaFuncSetAttribute(fused_kernel, cudaFuncAttributeMaxDynamicSharedMemorySize, fused_smem);

    prep_kernel<<<5, 128>>>(wq_v, wq_g, wk_v, wk_g, wv_v, wv_g, fc_v, fc_g, rel_k, rel_v);
    fused_kernel<<<NBF, 256, fused_smem>>>(inQ, inK, inV, w1, w2, attn_out);
    stats_kernel<<<D_, 256>>>(gamma, beta);
    out_kernel<<<NBO, 256>>>(inV, out);
}